// round 11
// baseline (speedup 1.0000x reference)
#include <cuda_runtime.h>
#include <cuda_fp16.h>

#define WSZ 21
#define KW  43
#define IH  128
#define IW  128
#define IB  2
#define NPIX (IB*IH*IW)   // 32768
#define NMAIN (IB*IH*KW)  // 11008

__device__ float4 g_s4[NPIX];    // smooth channels, .w = |s|^2
__device__ float4 g_o4[NPIX];    // orig channels,   .w = |o|^2
__device__ uint2  g_oh[NPIX];    // fp16 pack: (o.x,o.y) , (o.z, -|o|^2/2)
__device__ float  g_mask[NPIX];  // m_large
__device__ float4 g_tmp4[NPIX];  // conv scratch (horizontal pass)
__device__ float  g_swtab[KW+1]; // [KW] = total 2D spatial weight
__device__ double g_partial[32];
__device__ unsigned g_done;

__device__ __forceinline__ float ex2f(float x) {
    float y; asm("ex2.approx.ftz.f32 %0, %1;" : "=f"(y) : "f"(x)); return y;
}
__device__ __forceinline__ float lg2f(float x) {
    float y; asm("lg2.approx.ftz.f32 %0, %1;" : "=f"(y) : "f"(x)); return y;
}
__device__ __forceinline__ int refl(int p, int n) {
    if (p < 0) p = -p;
    if (p >= n) p = 2*n - 2 - p;
    return p;
}
__device__ __forceinline__ unsigned h2u(__half2 h) {
    unsigned u; asm("mov.b32 %0, %1;" : "=r"(u) : "r"(*(unsigned*)&h)); return u;
}

// Fused prep + horizontal conv. One block per (batch,row), 128 threads (one per col).
__global__ void __launch_bounds__(128) prep_kernel(const float* __restrict__ orig,
                                                   const float* __restrict__ smo) {
    __shared__ float sp[18][128];           // 6 planes x 3 rows
    __shared__ float4 srow4[IW + 2*WSZ];
    __shared__ float  swy[KW];

    int t  = threadIdx.x;
    int rg = blockIdx.x;          // 0..255
    int b  = rg >> 7;
    int r  = rg & (IH-1);

    if (rg == 0) {                // per-launch global inits
        if (t < 32) g_partial[t] = 0.0;
        if (t == 32) g_done = 0u;
        if (t == 64) {
            float s1 = 0.f;
            for (int x = -WSZ; x <= WSZ; ++x) s1 += expf(-(1.0f/98.0f)*(float)(x*x));
            g_swtab[KW] = s1 * s1;
        }
    }
    if (t < KW) {
        float d = (float)(t - WSZ);
        float w = expf(-(1.0f/98.0f) * d * d);
        swy[t] = w;
        if (rg == 0) g_swtab[t] = w;
    }

    int rm = refl(r-1, IH), rp = refl(r+1, IH);
    for (int i = t; i < 576; i += 128) {
        int seg = i >> 5;         // 0..17
        int v   = i & 31;
        int p   = seg / 3;        // plane
        int k   = seg % 3;        // row select
        int rr  = (k == 0) ? rm : ((k == 1) ? r : rp);
        const float* src = (p < 3 ? orig : smo) + b*3*IH*IW + (p % 3)*IH*IW + rr*IW;
        ((float4*)&sp[seg][0])[v] = ((const float4*)src)[v];
    }
    __syncthreads();

    int c = t;
    int cm = c ? c - 1 : 1;
    int cp = (c < IW-1) ? c + 1 : IW - 2;
    float eo = 0.f, es = 0.f, oo[3], ss[3];
    #pragma unroll
    for (int ch = 0; ch < 3; ++ch) {
        int s0 = ch*3;
        float a00=sp[s0+0][cm], a01=sp[s0+0][c], a02=sp[s0+0][cp];
        float a10=sp[s0+1][cm], a11=sp[s0+1][c], a12=sp[s0+1][cp];
        float a20=sp[s0+2][cm], a21=sp[s0+2][c], a22=sp[s0+2][cp];
        float gx = (a02 + 2.f*a12 + a22) - (a00 + 2.f*a10 + a20);
        float gy = (a20 + 2.f*a21 + a22) - (a00 + 2.f*a01 + a02);
        eo += sqrtf(gx*gx + gy*gy);
        oo[ch] = a11;
        int s1 = 9 + ch*3;
        float b00=sp[s1+0][cm], b01=sp[s1+0][c], b02=sp[s1+0][cp];
        float b10=sp[s1+1][cm], b11=sp[s1+1][c], b12=sp[s1+1][cp];
        float b20=sp[s1+2][cm], b21=sp[s1+2][c], b22=sp[s1+2][cp];
        float hx = (b02 + 2.f*b12 + b22) - (b00 + 2.f*b10 + b20);
        float hy = (b20 + 2.f*b21 + b22) - (b00 + 2.f*b01 + b02);
        es += sqrtf(hx*hx + hy*hy);
        ss[ch] = b11;
    }
    int idx = b*IH*IW + r*IW + c;
    float sw = ss[0]*ss[0]+ss[1]*ss[1]+ss[2]*ss[2];
    float ow = oo[0]*oo[0]+oo[1]*oo[1]+oo[2]*oo[2];
    g_mask[idx] = ((eo < 20.f) && (es - eo > 10.f)) ? 1.f : 0.f;
    float4 s4v = make_float4(ss[0], ss[1], ss[2], sw);
    g_s4[idx] = s4v;
    g_o4[idx] = make_float4(oo[0], oo[1], oo[2], ow);
    g_oh[idx] = make_uint2(h2u(__floats2half2_rn(oo[0], oo[1])),
                           h2u(__floats2half2_rn(oo[2], -0.5f*ow)));

    // horizontal conv of s4 (pass 1 of separable Gaussian)
    srow4[WSZ + t] = s4v;
    __syncthreads();
    if (t < 2*WSZ) {
        int q = (t < WSZ) ? t : (IW + t);
        int col = refl(q - WSZ, IW);
        srow4[q] = srow4[WSZ + col];
    }
    __syncthreads();
    float4 a = make_float4(0.f, 0.f, 0.f, 0.f);
    #pragma unroll 4
    for (int j = 0; j < KW; ++j) {
        float  w = swy[j];
        float4 v = srow4[t + j];
        a.x = fmaf(w, v.x, a.x);
        a.y = fmaf(w, v.y, a.y);
        a.z = fmaf(w, v.z, a.z);
        a.w = fmaf(w, v.w, a.w);
    }
    g_tmp4[idx] = a;
}

// m_small screen+replay (R7-validated body) + merged large term + last-block finalize.
__global__ void __launch_bounds__(128) main_kernel(float* __restrict__ out) {
    __shared__ alignas(8) uint2  sH[IW + 2*WSZ + 2];
    __shared__ float4 sO[IW + 2*WSZ];
    __shared__ float4 sS[IW + 2*WSZ];
    __shared__ float  wpart[4];
    __shared__ unsigned lastflag;

    int t  = threadIdx.x;
    int bx = blockIdx.x;
    int xob = bx % KW;           // 0..42
    int rg = bx / KW;            // 0..255
    int b  = rg >> 7;
    int r  = rg & (IH-1);

    float acc = 0.f;

    // ---- merged large term: blocks 0..127 each handle 256 pixels (2/thread) ----
    if (bx < NPIX/256) {
        #pragma unroll
        for (int half = 0; half < 2; ++half) {
            int idx = bx*256 + half*128 + t;
            int lc = idx & (IW-1);
            int lr = (idx >> 7) & (IH-1);
            int lb = idx >> 14;
            float4 a = make_float4(0.f, 0.f, 0.f, 0.f);
            #pragma unroll 4
            for (int j = 0; j < KW; ++j) {
                int rr = refl(lr + j - WSZ, IH);
                float  w = g_swtab[j];
                float4 v = g_tmp4[lb*IH*IW + rr*IW + lc];
                a.x = fmaf(w, v.x, a.x);
                a.y = fmaf(w, v.y, a.y);
                a.z = fmaf(w, v.z, a.z);
                a.w = fmaf(w, v.w, a.w);
            }
            float4 s  = g_s4[idx];
            float Wsum = g_swtab[KW];
            float dt = s.x*a.x + s.y*a.y + s.z*a.z;
            acc += g_mask[idx] * (fmaf(Wsum, s.w, a.w) - 2.f*dt);
        }
    }

    // ---- fill smem rows ----
    int nbase = b*IH*IW + refl(r + xob - WSZ, IH)*IW;
    for (int q = t; q < IW + 2*WSZ; q += 128) {
        int cj = refl(q - WSZ, IW);
        sH[q] = g_oh[nbase + cj];
        sO[q] = g_o4[nbase + cj];
        sS[q] = g_s4[nbase + cj];
    }
    __syncthreads();

    int cidx = b*IH*IW + r*IW + t;
    float4 oc = g_o4[cidx];
    float4 sc = g_s4[cidx];
    bool msnz = (g_mask[cidx] == 0.f);     // m_small != 0
    float thr_f = msnz ? (0.5f*oc.w - 0.18022f - 0.06f) : 3.0e38f;
    __half  thr_h = __float2half_rn(thr_f);
    __half2 ca = __floats2half2_rn(oc.x, oc.y);
    __half2 cb = __floats2half2_rn(oc.z, 1.0f);

    unsigned mlo = 0u, mhi = 0u;
    #pragma unroll
    for (int j = 0; j < KW; ++j) {
        uint2 u = sH[t + j];
        __half2 a  = *(__half2*)&u.x;
        __half2 bb = *(__half2*)&u.y;
        __half2 v2 = __hfma2(cb, bb, __hmul2(ca, a));
        __half2 s2 = __hadd2(v2, __lowhigh2highlow(v2));
        bool p = __hgt(__low2half(s2), thr_h);
        if (j < 32) { if (p) mlo |= (1u << j); }
        else        { if (p) mhi |= (1u << (j - 32)); }
    }

    float c0 = -72.13475204444817f * oc.w;
    while (mlo) {
        int j = __ffs(mlo) - 1; mlo &= mlo - 1;
        float4 o = sO[t + j];
        float4 s = sS[t + j];
        float dot = fmaf(oc.z, o.z, fmaf(oc.y, o.y, oc.x * o.x));
        float arg = fmaf(144.26950408889634f, dot, fmaf(-72.13475204444817f, o.w, c0));
        float wr = ex2f(arg);
        float p0 = ex2f(0.8f * lg2f(fabsf(sc.x - s.x)));
        float p1 = ex2f(0.8f * lg2f(fabsf(sc.y - s.y)));
        float p2 = ex2f(0.8f * lg2f(fabsf(sc.z - s.z)));
        acc = fmaf(wr, p0 + p1 + p2, acc);
    }
    while (mhi) {
        int j = __ffs(mhi) - 1 + 32; mhi &= mhi - 1;
        float4 o = sO[t + j];
        float4 s = sS[t + j];
        float dot = fmaf(oc.z, o.z, fmaf(oc.y, o.y, oc.x * o.x));
        float arg = fmaf(144.26950408889634f, dot, fmaf(-72.13475204444817f, o.w, c0));
        float wr = ex2f(arg);
        float p0 = ex2f(0.8f * lg2f(fabsf(sc.x - s.x)));
        float p1 = ex2f(0.8f * lg2f(fabsf(sc.y - s.y)));
        float p2 = ex2f(0.8f * lg2f(fabsf(sc.z - s.z)));
        acc = fmaf(wr, p0 + p1 + p2, acc);
    }

    #pragma unroll
    for (int off = 16; off; off >>= 1)
        acc += __shfl_xor_sync(0xffffffffu, acc, off);
    if ((t & 31) == 0) wpart[t >> 5] = acc;
    __syncthreads();
    if (t == 0) {
        float bs = wpart[0] + wpart[1] + wpart[2] + wpart[3];
        atomicAdd(&g_partial[bx & 31], (double)bs);
        __threadfence();
        unsigned v = atomicAdd(&g_done, 1u);
        lastflag = (v == NMAIN - 1) ? 1u : 0u;
    }
    __syncthreads();
    if (lastflag && t < 32) {
        double d = g_partial[t];
        #pragma unroll
        for (int off = 16; off; off >>= 1)
            d += __shfl_xor_sync(0xffffffffu, d, off);
        if (t == 0) out[0] = (float)(d / (double)NPIX);
    }
}

extern "C" void kernel_launch(void* const* d_in, const int* in_sizes, int n_in,
                              void* d_out, int out_size) {
    const float* orig = (const float*)d_in[0];
    const float* smo  = (const float*)d_in[1];
    float* out = (float*)d_out;
    (void)in_sizes; (void)n_in; (void)out_size;

    prep_kernel<<<IB*IH, 128>>>(orig, smo);   // fused prep + horizontal conv
    main_kernel<<<NMAIN, 128>>>(out);         // large merged into blocks 0..127
}

// round 12
// speedup vs baseline: 1.3894x; 1.3894x over previous
#include <cuda_runtime.h>

#define WSZ 21
#define KW  43
#define IH  128
#define IW  128
#define IB  2
#define NPIX (IB*IH*IW)   // 32768
#define NMAIN (IB*IH*KW)  // 11008

__device__ float4 g_s4[NPIX];    // smooth channels, .w = |s|^2
__device__ float4 g_o4[NPIX];    // orig channels,   .w = |o|^2
__device__ unsigned g_q[NPIX];   // int8 pack: round(16*o)+128 per channel, 4th byte 128
__device__ float  g_mask[NPIX];  // m_large
__device__ float4 g_tmp4[NPIX];  // conv scratch (horizontal pass)
__device__ float  g_swtab[KW+1]; // [KW] = total 2D spatial weight
__device__ double g_partial[256];

__device__ __forceinline__ float ex2f(float x) {
    float y; asm("ex2.approx.ftz.f32 %0, %1;" : "=f"(y) : "f"(x)); return y;
}
__device__ __forceinline__ float lg2f(float x) {
    float y; asm("lg2.approx.ftz.f32 %0, %1;" : "=f"(y) : "f"(x)); return y;
}
__device__ __forceinline__ int refl(int p, int n) {
    if (p < 0) p = -p;
    if (p >= n) p = 2*n - 2 - p;
    return p;
}
__device__ __forceinline__ unsigned qpack(float x) {
    int v = __float2int_rn(16.f * x) + 128;
    v = v < 0 ? 0 : (v > 255 ? 255 : v);
    return (unsigned)v;
}

// Fused prep + horizontal conv. One block per (batch,row), 128 threads (one per col).
__global__ void __launch_bounds__(128) prep_kernel(const float* __restrict__ orig,
                                                   const float* __restrict__ smo) {
    __shared__ float sp[18][128];           // 6 planes x 3 rows
    __shared__ float4 srow4[IW + 2*WSZ];
    __shared__ float  swy[KW];

    int t  = threadIdx.x;
    int rg = blockIdx.x;          // 0..255
    int b  = rg >> 7;
    int r  = rg & (IH-1);

    if (rg == 0) {                // per-launch global inits
        g_partial[t] = 0.0;
        g_partial[t + 128] = 0.0;
        if (t == 0) {
            float s1 = 0.f;
            for (int x = -WSZ; x <= WSZ; ++x) s1 += expf(-(1.0f/98.0f)*(float)(x*x));
            g_swtab[KW] = s1 * s1;
        }
    }
    if (t < KW) {
        float d = (float)(t - WSZ);
        float w = expf(-(1.0f/98.0f) * d * d);
        swy[t] = w;
        if (rg == 0) g_swtab[t] = w;
    }

    int rm = refl(r-1, IH), rp = refl(r+1, IH);
    for (int i = t; i < 576; i += 128) {
        int seg = i >> 5;         // 0..17
        int v   = i & 31;
        int p   = seg / 3;        // plane
        int k   = seg % 3;        // row select
        int rr  = (k == 0) ? rm : ((k == 1) ? r : rp);
        const float* src = (p < 3 ? orig : smo) + b*3*IH*IW + (p % 3)*IH*IW + rr*IW;
        ((float4*)&sp[seg][0])[v] = ((const float4*)src)[v];
    }
    __syncthreads();

    int c = t;
    int cm = c ? c - 1 : 1;
    int cp = (c < IW-1) ? c + 1 : IW - 2;
    float eo = 0.f, es = 0.f, oo[3], ss[3];
    #pragma unroll
    for (int ch = 0; ch < 3; ++ch) {
        int s0 = ch*3;
        float a00=sp[s0+0][cm], a01=sp[s0+0][c], a02=sp[s0+0][cp];
        float a10=sp[s0+1][cm], a11=sp[s0+1][c], a12=sp[s0+1][cp];
        float a20=sp[s0+2][cm], a21=sp[s0+2][c], a22=sp[s0+2][cp];
        float gx = (a02 + 2.f*a12 + a22) - (a00 + 2.f*a10 + a20);
        float gy = (a20 + 2.f*a21 + a22) - (a00 + 2.f*a01 + a02);
        eo += sqrtf(gx*gx + gy*gy);
        oo[ch] = a11;
        int s1 = 9 + ch*3;
        float b00=sp[s1+0][cm], b01=sp[s1+0][c], b02=sp[s1+0][cp];
        float b10=sp[s1+1][cm], b11=sp[s1+1][c], b12=sp[s1+1][cp];
        float b20=sp[s1+2][cm], b21=sp[s1+2][c], b22=sp[s1+2][cp];
        float hx = (b02 + 2.f*b12 + b22) - (b00 + 2.f*b10 + b20);
        float hy = (b20 + 2.f*b21 + b22) - (b00 + 2.f*b01 + b02);
        es += sqrtf(hx*hx + hy*hy);
        ss[ch] = b11;
    }
    int idx = b*IH*IW + r*IW + c;
    float sw = ss[0]*ss[0]+ss[1]*ss[1]+ss[2]*ss[2];
    float ow = oo[0]*oo[0]+oo[1]*oo[1]+oo[2]*oo[2];
    g_mask[idx] = ((eo < 20.f) && (es - eo > 10.f)) ? 1.f : 0.f;
    float4 s4v = make_float4(ss[0], ss[1], ss[2], sw);
    g_s4[idx] = s4v;
    g_o4[idx] = make_float4(oo[0], oo[1], oo[2], ow);
    g_q[idx]  = qpack(oo[0]) | (qpack(oo[1]) << 8) | (qpack(oo[2]) << 16) | (128u << 24);

    // horizontal conv of s4 (pass 1 of separable Gaussian)
    srow4[WSZ + t] = s4v;
    __syncthreads();
    if (t < 2*WSZ) {
        int q = (t < WSZ) ? t : (IW + t);
        int col = refl(q - WSZ, IW);
        srow4[q] = srow4[WSZ + col];
    }
    __syncthreads();
    float4 a = make_float4(0.f, 0.f, 0.f, 0.f);
    #pragma unroll 4
    for (int j = 0; j < KW; ++j) {
        float  w = swy[j];
        float4 v = srow4[t + j];
        a.x = fmaf(w, v.x, a.x);
        a.y = fmaf(w, v.y, a.y);
        a.z = fmaf(w, v.z, a.z);
        a.w = fmaf(w, v.w, a.w);
    }
    g_tmp4[idx] = a;
}

// Vertical pass + m_large term reduce (exact closed form).
__global__ void __launch_bounds__(256) large_kernel() {
    __shared__ float wpart[8];
    int t   = threadIdx.x;
    int idx = blockIdx.x * 256 + t;
    int c = idx & (IW-1);
    int r = (idx >> 7) & (IH-1);
    int b = idx >> 14;
    float4 a = make_float4(0.f, 0.f, 0.f, 0.f);
    #pragma unroll 4
    for (int j = 0; j < KW; ++j) {
        int rr = refl(r + j - WSZ, IH);
        float  w = g_swtab[j];
        float4 v = g_tmp4[b*IH*IW + rr*IW + c];
        a.x = fmaf(w, v.x, a.x);
        a.y = fmaf(w, v.y, a.y);
        a.z = fmaf(w, v.z, a.z);
        a.w = fmaf(w, v.w, a.w);
    }
    float4 s  = g_s4[idx];
    float Wsum = g_swtab[KW];
    float dot = s.x*a.x + s.y*a.y + s.z*a.z;
    float val = g_mask[idx] * (fmaf(Wsum, s.w, a.w) - 2.f*dot);
    #pragma unroll
    for (int off = 16; off; off >>= 1)
        val += __shfl_xor_sync(0xffffffffu, val, off);
    if ((t & 31) == 0) wpart[t >> 5] = val;
    __syncthreads();
    if (t == 0) {
        float bs = 0.f;
        #pragma unroll
        for (int w = 0; w < 8; ++w) bs += wpart[w];
        atomicAdd(&g_partial[blockIdx.x & 255], (double)bs);
    }
}

// m_small term: int8/dp4a screen (smem) + exact fp32 replay (smem-staged).
// One block per (batch*row, x-offset), 128 threads. R7 structure.
__global__ void __launch_bounds__(128) main_kernel() {
    __shared__ unsigned sQ[IW + 2*WSZ + 2];
    __shared__ float4 sO[IW + 2*WSZ];
    __shared__ float4 sS[IW + 2*WSZ];
    __shared__ float  wpart[4];

    int t  = threadIdx.x;
    int bx = blockIdx.x;
    int xob = bx % KW;           // 0..42
    int rg = bx / KW;            // 0..255
    int b  = rg >> 7;
    int r  = rg & (IH-1);

    int nbase = b*IH*IW + refl(r + xob - WSZ, IH)*IW;
    for (int q = t; q < IW + 2*WSZ; q += 128) {
        int cj = refl(q - WSZ, IW);
        sQ[q] = g_q[nbase + cj];
        sO[q] = g_o4[nbase + cj];
        sS[q] = g_s4[nbase + cj];
    }
    __syncthreads();

    int cidx = b*IH*IW + r*IW + t;
    float4 oc = g_o4[cidx];
    float4 sc = g_s4[cidx];
    unsigned qc = g_q[cidx];
    bool msnz = (g_mask[cidx] == 0.f);     // m_small != 0
    int thr_i = msnz ? 128 : -1;           // dp <= thr; dp >= 0 so -1 kills all

    unsigned mlo = 0u, mhi = 0u;
    #pragma unroll
    for (int j = 0; j < KW; ++j) {
        unsigned d = __vabsdiffu4(qc, sQ[t + j]);
        int dp = __dp4a(d, d, 0u);
        bool p = (dp <= thr_i);
        if (j < 32) { if (p) mlo |= (1u << j); }
        else        { if (p) mhi |= (1u << (j - 32)); }
    }

    float acc = 0.f;
    while (mlo) {
        int j = __ffs(mlo) - 1; mlo &= mlo - 1;
        float4 o = sO[t + j];
        float4 s = sS[t + j];
        float u0 = oc.x - o.x, u1 = oc.y - o.y, u2 = oc.z - o.z;
        float rr = fmaf(u0, u0, fmaf(u1, u1, u2 * u2));
        float wr = ex2f(-72.13475204444817f * rr);
        float p0 = ex2f(0.8f * lg2f(fabsf(sc.x - s.x)));
        float p1 = ex2f(0.8f * lg2f(fabsf(sc.y - s.y)));
        float p2 = ex2f(0.8f * lg2f(fabsf(sc.z - s.z)));
        acc = fmaf(wr, p0 + p1 + p2, acc);
    }
    while (mhi) {
        int j = __ffs(mhi) - 1 + 32; mhi &= mhi - 1;
        float4 o = sO[t + j];
        float4 s = sS[t + j];
        float u0 = oc.x - o.x, u1 = oc.y - o.y, u2 = oc.z - o.z;
        float rr = fmaf(u0, u0, fmaf(u1, u1, u2 * u2));
        float wr = ex2f(-72.13475204444817f * rr);
        float p0 = ex2f(0.8f * lg2f(fabsf(sc.x - s.x)));
        float p1 = ex2f(0.8f * lg2f(fabsf(sc.y - s.y)));
        float p2 = ex2f(0.8f * lg2f(fabsf(sc.z - s.z)));
        acc = fmaf(wr, p0 + p1 + p2, acc);
    }

    #pragma unroll
    for (int off = 16; off; off >>= 1)
        acc += __shfl_xor_sync(0xffffffffu, acc, off);
    if ((t & 31) == 0) wpart[t >> 5] = acc;
    __syncthreads();
    if (t == 0) {
        float bs = wpart[0] + wpart[1] + wpart[2] + wpart[3];
        atomicAdd(&g_partial[bx & 255], (double)bs);
    }
}

__global__ void finalize_kernel(float* __restrict__ out) {
    __shared__ double sh[256];
    int t = threadIdx.x;
    sh[t] = g_partial[t];
    __syncthreads();
    for (int s = 128; s > 0; s >>= 1) {
        if (t < s) sh[t] += sh[t + s];
        __syncthreads();
    }
    if (t == 0) out[0] = (float)(sh[0] / (double)NPIX);
}

extern "C" void kernel_launch(void* const* d_in, const int* in_sizes, int n_in,
                              void* d_out, int out_size) {
    const float* orig = (const float*)d_in[0];
    const float* smo  = (const float*)d_in[1];
    float* out = (float*)d_out;
    (void)in_sizes; (void)n_in; (void)out_size;

    prep_kernel<<<IB*IH, 128>>>(orig, smo);   // fused prep + horizontal conv
    large_kernel<<<NPIX/256, 256>>>();
    main_kernel<<<NMAIN, 128>>>();            // 11008 blocks, R7 structure
    finalize_kernel<<<1, 256>>>(out);
}